// round 1
// baseline (speedup 1.0000x reference)
#include <cuda_runtime.h>
#include <cstdint>

#define BATCH 4
#define SEQ   4096
#define DMODEL 1024
#define DIM   128
#define NE    384   // 3*DIM

// Scratch for de-interleaved projections (no cudaMalloc allowed)
__device__ float g_Q[BATCH * SEQ * DIM];
__device__ float g_K[BATCH * SEQ * DIM];
__device__ float g_V[BATCH * SEQ * DIM];

// ---------------------------------------------------------------------------
// Kernel 1: qkv = x @ W + b ; scatter de-interleaved into g_Q/g_K/g_V
// GEMM: M = BATCH*SEQ = 16384, K = 1024, N = 384
// Tiles: BM=128, BN=64, BK=16. 256 threads as 16x16; each thread 8x4 outputs.
// ---------------------------------------------------------------------------
__global__ __launch_bounds__(256)
void qkv_kernel(const float* __restrict__ x,
                const float* __restrict__ W,
                const float* __restrict__ bias) {
    __shared__ float As[16][128];  // [k][m]
    __shared__ float Bs[16][64];   // [k][n]

    const int bm = blockIdx.x;           // 0..127
    const int bn = blockIdx.y;           // 0..5
    const int tid = threadIdx.x;
    const int ty = tid >> 4;             // 0..15 (M direction)
    const int tx = tid & 15;             // 0..15 (N direction)
    const int row0 = bm * 128;
    const int col0 = bn * 64;

    float acc[8][4];
#pragma unroll
    for (int i = 0; i < 8; i++)
#pragma unroll
        for (int j = 0; j < 4; j++) acc[i][j] = 0.0f;

    for (int k0 = 0; k0 < DMODEL; k0 += 16) {
        // A tile: 128 rows x 16 k = 512 float4 slots, 2 per thread
#pragma unroll
        for (int it = 0; it < 2; it++) {
            int slot = tid + it * 256;          // 0..511
            int r  = slot >> 2;                 // 0..127
            int c4 = slot & 3;                  // 0..3  (4 floats each)
            float4 v = *(const float4*)(x + (size_t)(row0 + r) * DMODEL + k0 + c4 * 4);
            As[c4 * 4 + 0][r] = v.x;
            As[c4 * 4 + 1][r] = v.y;
            As[c4 * 4 + 2][r] = v.z;
            As[c4 * 4 + 3][r] = v.w;
        }
        // B tile: 16 k-rows x 64 n = 256 float4 slots, 1 per thread
        {
            int r  = tid >> 4;                  // 0..15
            int c4 = tid & 15;                  // 0..15
            float4 v = *(const float4*)(W + (size_t)(k0 + r) * NE + col0 + c4 * 4);
            *(float4*)&Bs[r][c4 * 4] = v;
        }
        __syncthreads();

#pragma unroll
        for (int kk = 0; kk < 16; kk++) {
            float4 A0 = *(const float4*)&As[kk][ty * 8];
            float4 A1 = *(const float4*)&As[kk][ty * 8 + 4];
            float4 Bv = *(const float4*)&Bs[kk][tx * 4];
            float a[8] = {A0.x, A0.y, A0.z, A0.w, A1.x, A1.y, A1.z, A1.w};
            float bb[4] = {Bv.x, Bv.y, Bv.z, Bv.w};
#pragma unroll
            for (int i = 0; i < 8; i++)
#pragma unroll
                for (int j = 0; j < 4; j++) acc[i][j] += a[i] * bb[j];
        }
        __syncthreads();
    }

    // Epilogue: bias + de-interleave scatter. e = d*3 + which
#pragma unroll
    for (int j = 0; j < 4; j++) {
        int e = col0 + tx * 4 + j;
        float bj = bias[e];
        int d = e / 3;
        int which = e % 3;
        float* dst = (which == 0) ? g_Q : ((which == 1) ? g_K : g_V);
#pragma unroll
        for (int i = 0; i < 8; i++) {
            int row = row0 + ty * 8 + i;
            dst[(size_t)row * DIM + d] = acc[i][j] + bj;
        }
    }
}

// ---------------------------------------------------------------------------
// Kernel 2: flash attention, fp32. One block = 64 queries of one batch.
// 256 threads as 16(ty: q) x 16(tx: k / d). Key tiles of 64.
// Dynamic smem: Qs(64x128) Ks(64x128) Vs(64x128) Ps(64x64) = 112 KB
// ---------------------------------------------------------------------------
#define ATTN_SMEM_BYTES ((3 * 64 * 128 + 64 * 64) * 4)

__global__ __launch_bounds__(256, 2)
void attn_kernel(float* __restrict__ out) {
    extern __shared__ float sm[];
    float* Qs = sm;                  // [64][128]
    float* Ks = sm + 64 * 128;       // [64][128]
    float* Vs = sm + 2 * 64 * 128;   // [64][128]
    float* Ps = sm + 3 * 64 * 128;   // [64][64]

    const int b  = blockIdx.y;
    const int q0 = blockIdx.x * 64;
    const int tid = threadIdx.x;
    const int ty = tid >> 4;   // q-row group
    const int tx = tid & 15;   // k-col / d group

    const float* Qg = g_Q + (size_t)b * SEQ * DIM;
    const float* Kg = g_K + (size_t)b * SEQ * DIM;
    const float* Vg = g_V + (size_t)b * SEQ * DIM;

    const float scale = 0.08838834764831845f;  // 128^-0.5 (folded into Q)

    // Load + pre-scale Q tile
    for (int i = tid; i < 64 * 32; i += 256) {
        int r = i >> 5, c = (i & 31) << 2;
        float4 v = *(const float4*)(Qg + (size_t)(q0 + r) * DIM + c);
        v.x *= scale; v.y *= scale; v.z *= scale; v.w *= scale;
        *(float4*)&Qs[r * 128 + c] = v;
    }

    float m_i[4], l_i[4], o[4][8];
#pragma unroll
    for (int i = 0; i < 4; i++) {
        m_i[i] = -1e30f; l_i[i] = 0.0f;
#pragma unroll
        for (int j = 0; j < 8; j++) o[i][j] = 0.0f;
    }

    for (int k0 = 0; k0 < SEQ; k0 += 64) {
        __syncthreads();  // protect Ks/Vs/Ps from previous iteration readers
        for (int i = tid; i < 64 * 32; i += 256) {
            int r = i >> 5, c = (i & 31) << 2;
            *(float4*)&Ks[r * 128 + c] = *(const float4*)(Kg + (size_t)(k0 + r) * DIM + c);
            *(float4*)&Vs[r * 128 + c] = *(const float4*)(Vg + (size_t)(k0 + r) * DIM + c);
        }
        __syncthreads();

        // S = Qs @ Ks^T   (Q pre-scaled). Thread owns rows ty*4.., cols tx*4..
        float s[4][4];
#pragma unroll
        for (int i = 0; i < 4; i++)
#pragma unroll
            for (int j = 0; j < 4; j++) s[i][j] = 0.0f;

        for (int d0 = 0; d0 < 128; d0 += 4) {
            float4 qa[4], kb[4];
#pragma unroll
            for (int i = 0; i < 4; i++) qa[i] = *(const float4*)&Qs[(ty * 4 + i) * 128 + d0];
#pragma unroll
            for (int j = 0; j < 4; j++) kb[j] = *(const float4*)&Ks[(tx * 4 + j) * 128 + d0];
#pragma unroll
            for (int i = 0; i < 4; i++)
#pragma unroll
                for (int j = 0; j < 4; j++) {
                    s[i][j] += qa[i].x * kb[j].x;
                    s[i][j] += qa[i].y * kb[j].y;
                    s[i][j] += qa[i].z * kb[j].z;
                    s[i][j] += qa[i].w * kb[j].w;
                }
        }

        // Online softmax per query row; reductions across the 16 tx lanes
#pragma unroll
        for (int i = 0; i < 4; i++) {
            float rmax = fmaxf(fmaxf(s[i][0], s[i][1]), fmaxf(s[i][2], s[i][3]));
#pragma unroll
            for (int off = 1; off < 16; off <<= 1)
                rmax = fmaxf(rmax, __shfl_xor_sync(0xffffffffu, rmax, off));
            float mnew = fmaxf(m_i[i], rmax);
            float p0 = __expf(s[i][0] - mnew);
            float p1 = __expf(s[i][1] - mnew);
            float p2 = __expf(s[i][2] - mnew);
            float p3 = __expf(s[i][3] - mnew);
            float rsum = (p0 + p1) + (p2 + p3);
#pragma unroll
            for (int off = 1; off < 16; off <<= 1)
                rsum += __shfl_xor_sync(0xffffffffu, rsum, off);
            float corr = __expf(m_i[i] - mnew);
            l_i[i] = l_i[i] * corr + rsum;
            m_i[i] = mnew;
#pragma unroll
            for (int j = 0; j < 8; j++) o[i][j] *= corr;
            float4 pv = make_float4(p0, p1, p2, p3);
            *(float4*)&Ps[(ty * 4 + i) * 64 + tx * 4] = pv;
        }
        __syncthreads();

        // O += P @ V. Thread owns d = {tx*4..tx*4+3, 64+tx*4..64+tx*4+3}
        for (int kk0 = 0; kk0 < 64; kk0 += 4) {
            float pp[4][4];
#pragma unroll
            for (int i = 0; i < 4; i++) {
                float4 p4 = *(const float4*)&Ps[(ty * 4 + i) * 64 + kk0];
                pp[i][0] = p4.x; pp[i][1] = p4.y; pp[i][2] = p4.z; pp[i][3] = p4.w;
            }
#pragma unroll
            for (int u = 0; u < 4; u++) {
                float4 v0 = *(const float4*)&Vs[(kk0 + u) * 128 + tx * 4];
                float4 v1 = *(const float4*)&Vs[(kk0 + u) * 128 + 64 + tx * 4];
#pragma unroll
                for (int i = 0; i < 4; i++) {
                    float p = pp[i][u];
                    o[i][0] += p * v0.x; o[i][1] += p * v0.y;
                    o[i][2] += p * v0.z; o[i][3] += p * v0.w;
                    o[i][4] += p * v1.x; o[i][5] += p * v1.y;
                    o[i][6] += p * v1.z; o[i][7] += p * v1.w;
                }
            }
        }
    }

    // Epilogue: normalize and store
#pragma unroll
    for (int i = 0; i < 4; i++) {
        float inv = 1.0f / l_i[i];
        size_t base = ((size_t)b * SEQ + q0 + ty * 4 + i) * DIM;
        float4 r0 = make_float4(o[i][0] * inv, o[i][1] * inv, o[i][2] * inv, o[i][3] * inv);
        float4 r1 = make_float4(o[i][4] * inv, o[i][5] * inv, o[i][6] * inv, o[i][7] * inv);
        *(float4*)&out[base + tx * 4] = r0;
        *(float4*)&out[base + 64 + tx * 4] = r1;
    }
}

// ---------------------------------------------------------------------------
extern "C" void kernel_launch(void* const* d_in, const int* in_sizes, int n_in,
                              void* d_out, int out_size) {
    const float* x    = (const float*)d_in[0];
    const float* W    = (const float*)d_in[1];
    const float* bias = (const float*)d_in[2];
    float* out = (float*)d_out;

    // QKV projection: grid 128 (M tiles) x 6 (N tiles)
    dim3 g1(128, 6);
    qkv_kernel<<<g1, 256>>>(x, W, bias);

    // Attention: 64 q-tiles x 4 batches; 112 KB dynamic smem
    cudaFuncSetAttribute(attn_kernel, cudaFuncAttributeMaxDynamicSharedMemorySize,
                         ATTN_SMEM_BYTES);
    dim3 g2(SEQ / 64, BATCH);
    attn_kernel<<<g2, 256, ATTN_SMEM_BYTES>>>(out);
}

// round 2
// speedup vs baseline: 4.5139x; 4.5139x over previous
#include <cuda_runtime.h>
#include <cstdint>

#define BATCH 4
#define SEQ   4096
#define DMODEL 1024
#define DIM   128
#define NE    384   // 3*DIM

// Scratch for de-interleaved projections (no cudaMalloc allowed)
__device__ float g_Q[BATCH * SEQ * DIM];
__device__ float g_K[BATCH * SEQ * DIM];
__device__ float g_V[BATCH * SEQ * DIM];

// ---------------------------------------------------------------------------
// helpers
// ---------------------------------------------------------------------------
__device__ __forceinline__ uint32_t f2tf(float x) {
    uint32_t r;
    asm("cvt.rna.tf32.f32 %0, %1;" : "=r"(r) : "f"(x));
    return r;
}

__device__ __forceinline__ void mma_tf32(float* d, const uint32_t* a, const uint32_t* b) {
    asm volatile(
        "mma.sync.aligned.m16n8k8.row.col.f32.tf32.tf32.f32 "
        "{%0,%1,%2,%3}, {%4,%5,%6,%7}, {%8,%9}, {%0,%1,%2,%3};"
        : "+f"(d[0]), "+f"(d[1]), "+f"(d[2]), "+f"(d[3])
        : "r"(a[0]), "r"(a[1]), "r"(a[2]), "r"(a[3]), "r"(b[0]), "r"(b[1]));
}

// exp2 entirely on the FMA/ALU pipes (no MUFU). x <= 0 expected; clamped.
__device__ __forceinline__ float fast_exp2(float x) {
    x = fmaxf(x, -126.0f);
    float r = x + 12582912.0f;            // round-to-nearest-int via magic
    float i = r - 12582912.0f;
    float f = x - i;                      // f in [-0.5, 0.5]
    float p = 1.3333558146428443e-3f;
    p = fmaf(p, f, 9.618129107628477e-3f);
    p = fmaf(p, f, 5.5504108664821576e-2f);
    p = fmaf(p, f, 2.402265069591007e-1f);
    p = fmaf(p, f, 6.931471805599453e-1f);
    p = fmaf(p, f, 1.0f);
    float s = __int_as_float((__float_as_int(r) - 0x4B400000 + 127) << 23);
    return p * s;
}

// ---------------------------------------------------------------------------
// Kernel 1: qkv = x @ W + b, 3xTF32 split GEMM (fp32-level accuracy on tensor)
// M=16384 N=384 K=1024. BM=128 BN=128 BK=16, 8 warps: 4(m) x 2(n),
// warp tile 32x64 -> 2 m-tiles x 8 n-tiles of m16n8k8. 3 mma per tile-k:
// hi*hi + lo*hi + hi*lo.
// ---------------------------------------------------------------------------
#define ASTR 20
#define BSTR 136

__global__ __launch_bounds__(256)
void qkv_mma_kernel(const float* __restrict__ x,
                    const float* __restrict__ W,
                    const float* __restrict__ bias) {
    __shared__ float Ah[128 * ASTR], Al[128 * ASTR];
    __shared__ float Bh[16 * BSTR],  Bl[16 * BSTR];

    const int row0 = blockIdx.x * 128;
    const int col0 = blockIdx.y * 128;
    const int tid = threadIdx.x;
    const int w = tid >> 5, lane = tid & 31;
    const int g = lane >> 2, c = lane & 3;
    const int wm = w >> 1, wn = w & 1;

    float acc[2][8][4];
#pragma unroll
    for (int mt = 0; mt < 2; mt++)
#pragma unroll
        for (int nt = 0; nt < 8; nt++)
#pragma unroll
            for (int j = 0; j < 4; j++) acc[mt][nt][j] = 0.0f;

    for (int k0 = 0; k0 < DMODEL; k0 += 16) {
        __syncthreads();
        // A tile 128x16: 512 float4 slots, 2 per thread; split hi/lo
#pragma unroll
        for (int it = 0; it < 2; it++) {
            int slot = tid + it * 256;
            int r = slot >> 2, c4 = (slot & 3) * 4;
            float4 v = *(const float4*)(x + (size_t)(row0 + r) * DMODEL + k0 + c4);
            float h0 = __uint_as_float(f2tf(v.x));
            float h1 = __uint_as_float(f2tf(v.y));
            float h2 = __uint_as_float(f2tf(v.z));
            float h3 = __uint_as_float(f2tf(v.w));
            *(float4*)&Ah[r * ASTR + c4] = make_float4(h0, h1, h2, h3);
            float l0 = __uint_as_float(f2tf(v.x - h0));
            float l1 = __uint_as_float(f2tf(v.y - h1));
            float l2 = __uint_as_float(f2tf(v.z - h2));
            float l3 = __uint_as_float(f2tf(v.w - h3));
            *(float4*)&Al[r * ASTR + c4] = make_float4(l0, l1, l2, l3);
        }
        // B tile 16x128: 512 float4 slots, 2 per thread; split hi/lo
#pragma unroll
        for (int it = 0; it < 2; it++) {
            int slot = tid + it * 256;
            int r = slot >> 5, c4 = (slot & 31) * 4;
            float4 v = *(const float4*)(W + (size_t)(k0 + r) * NE + col0 + c4);
            float h0 = __uint_as_float(f2tf(v.x));
            float h1 = __uint_as_float(f2tf(v.y));
            float h2 = __uint_as_float(f2tf(v.z));
            float h3 = __uint_as_float(f2tf(v.w));
            *(float4*)&Bh[r * BSTR + c4] = make_float4(h0, h1, h2, h3);
            float l0 = __uint_as_float(f2tf(v.x - h0));
            float l1 = __uint_as_float(f2tf(v.y - h1));
            float l2 = __uint_as_float(f2tf(v.z - h2));
            float l3 = __uint_as_float(f2tf(v.w - h3));
            *(float4*)&Bl[r * BSTR + c4] = make_float4(l0, l1, l2, l3);
        }
        __syncthreads();

#pragma unroll
        for (int ks = 0; ks < 2; ks++) {
            uint32_t ah[2][4], al[2][4];
#pragma unroll
            for (int mt = 0; mt < 2; mt++) {
                int ar = wm * 32 + mt * 16 + g;
                ah[mt][0] = __float_as_uint(Ah[ar * ASTR + ks * 8 + c]);
                ah[mt][1] = __float_as_uint(Ah[(ar + 8) * ASTR + ks * 8 + c]);
                ah[mt][2] = __float_as_uint(Ah[ar * ASTR + ks * 8 + c + 4]);
                ah[mt][3] = __float_as_uint(Ah[(ar + 8) * ASTR + ks * 8 + c + 4]);
                al[mt][0] = __float_as_uint(Al[ar * ASTR + ks * 8 + c]);
                al[mt][1] = __float_as_uint(Al[(ar + 8) * ASTR + ks * 8 + c]);
                al[mt][2] = __float_as_uint(Al[ar * ASTR + ks * 8 + c + 4]);
                al[mt][3] = __float_as_uint(Al[(ar + 8) * ASTR + ks * 8 + c + 4]);
            }
#pragma unroll
            for (int nt = 0; nt < 8; nt++) {
                int bc = wn * 64 + nt * 8 + g;
                uint32_t bh[2], bl[2];
                bh[0] = __float_as_uint(Bh[(ks * 8 + c) * BSTR + bc]);
                bh[1] = __float_as_uint(Bh[(ks * 8 + c + 4) * BSTR + bc]);
                bl[0] = __float_as_uint(Bl[(ks * 8 + c) * BSTR + bc]);
                bl[1] = __float_as_uint(Bl[(ks * 8 + c + 4) * BSTR + bc]);
#pragma unroll
                for (int mt = 0; mt < 2; mt++) {
                    mma_tf32(acc[mt][nt], ah[mt], bh);
                    mma_tf32(acc[mt][nt], al[mt], bh);
                    mma_tf32(acc[mt][nt], ah[mt], bl);
                }
            }
        }
    }

    // Epilogue: bias + de-interleave scatter (e = d*3 + which)
#pragma unroll
    for (int mt = 0; mt < 2; mt++) {
#pragma unroll
        for (int nt = 0; nt < 8; nt++) {
            int er = row0 + wm * 32 + mt * 16 + g;
            int ec = col0 + wn * 64 + nt * 8 + 2 * c;
#pragma unroll
            for (int j = 0; j < 4; j++) {
                int r = er + ((j >= 2) ? 8 : 0);
                int e = ec + (j & 1);
                float v = acc[mt][nt][j] + bias[e];
                int d = e / 3, wh = e % 3;
                float* dst = (wh == 0) ? g_Q : ((wh == 1) ? g_K : g_V);
                dst[(size_t)r * DIM + d] = v;
            }
        }
    }
}

// ---------------------------------------------------------------------------
// Kernel 2: flash attention with tf32 mma.sync.
// Block = 128 queries x one batch, 8 warps (warp w owns rows w*16..w*16+15).
// Key tiles of 64. S = Q@K^T (Q pre-scaled by 128^-0.5 * log2(e), softmax in
// log2 domain with FMA-pipe exp2). P routed through smem for D->A layout.
// ---------------------------------------------------------------------------
#define KSTR 132
#define VSTR 136
#define PSTR 68
#define ATTN_SMEM_BYTES ((64 * KSTR + 64 * VSTR + 128 * PSTR) * 4)

__global__ __launch_bounds__(256, 1)
void attn_kernel(float* __restrict__ out) {
    extern __shared__ float sm[];
    float* Ks = sm;                    // [64][132]
    float* Vs = Ks + 64 * KSTR;        // [64][136]
    float* Ps = Vs + 64 * VSTR;        // [128][68]

    const int b  = blockIdx.y;
    const int q0 = blockIdx.x * 128;
    const int tid = threadIdx.x;
    const int w = tid >> 5, lane = tid & 31;
    const int g = lane >> 2, c = lane & 3;

    const float* Qg = g_Q + (size_t)b * SEQ * DIM;
    const float* Kg = g_K + (size_t)b * SEQ * DIM;
    const float* Vg = g_V + (size_t)b * SEQ * DIM;

    // scale * log2(e): scores computed directly in log2 domain
    const float pre = 0.12751745f;

    // Q fragments held in registers for the whole block: 16 ksteps x 4 regs
    uint32_t qf[16][4];
    {
        int qr = q0 + w * 16 + g;
#pragma unroll
        for (int ks = 0; ks < 16; ks++) {
            qf[ks][0] = f2tf(Qg[(size_t)qr * DIM + ks * 8 + c] * pre);
            qf[ks][1] = f2tf(Qg[(size_t)(qr + 8) * DIM + ks * 8 + c] * pre);
            qf[ks][2] = f2tf(Qg[(size_t)qr * DIM + ks * 8 + c + 4] * pre);
            qf[ks][3] = f2tf(Qg[(size_t)(qr + 8) * DIM + ks * 8 + c + 4] * pre);
        }
    }

    float o[16][4];
#pragma unroll
    for (int nt = 0; nt < 16; nt++)
#pragma unroll
        for (int j = 0; j < 4; j++) o[nt][j] = 0.0f;
    float m0 = -1e30f, m1 = -1e30f, l0 = 0.0f, l1 = 0.0f;

    for (int k0 = 0; k0 < SEQ; k0 += 64) {
        __syncthreads();
        // Load K,V tile (64 x 128 each), convert to tf32 at store
        for (int i = tid; i < 64 * 32; i += 256) {
            int r = i >> 5, cc = (i & 31) * 4;
            float4 kv = *(const float4*)(Kg + (size_t)(k0 + r) * DIM + cc);
            float4 vv = *(const float4*)(Vg + (size_t)(k0 + r) * DIM + cc);
            *(float4*)&Ks[r * KSTR + cc] = make_float4(
                __uint_as_float(f2tf(kv.x)), __uint_as_float(f2tf(kv.y)),
                __uint_as_float(f2tf(kv.z)), __uint_as_float(f2tf(kv.w)));
            *(float4*)&Vs[r * VSTR + cc] = make_float4(
                __uint_as_float(f2tf(vv.x)), __uint_as_float(f2tf(vv.y)),
                __uint_as_float(f2tf(vv.z)), __uint_as_float(f2tf(vv.w)));
        }
        __syncthreads();

        // ---- S = Q @ K^T (in log2 units) ----
        float s[8][4];
#pragma unroll
        for (int nt = 0; nt < 8; nt++) {
            s[nt][0] = 0.0f; s[nt][1] = 0.0f; s[nt][2] = 0.0f; s[nt][3] = 0.0f;
#pragma unroll
            for (int ks = 0; ks < 16; ks++) {
                uint32_t bf[2];
                bf[0] = __float_as_uint(Ks[(nt * 8 + g) * KSTR + ks * 8 + c]);
                bf[1] = __float_as_uint(Ks[(nt * 8 + g) * KSTR + ks * 8 + c + 4]);
                mma_tf32(s[nt], qf[ks], bf);
            }
        }

        // ---- online softmax (rows g and g+8 of this warp's 16) ----
        float rmax0 = -1e30f, rmax1 = -1e30f;
#pragma unroll
        for (int nt = 0; nt < 8; nt++) {
            rmax0 = fmaxf(rmax0, fmaxf(s[nt][0], s[nt][1]));
            rmax1 = fmaxf(rmax1, fmaxf(s[nt][2], s[nt][3]));
        }
        rmax0 = fmaxf(rmax0, __shfl_xor_sync(0xffffffffu, rmax0, 1));
        rmax0 = fmaxf(rmax0, __shfl_xor_sync(0xffffffffu, rmax0, 2));
        rmax1 = fmaxf(rmax1, __shfl_xor_sync(0xffffffffu, rmax1, 1));
        rmax1 = fmaxf(rmax1, __shfl_xor_sync(0xffffffffu, rmax1, 2));

        float mn0 = fmaxf(m0, rmax0), mn1 = fmaxf(m1, rmax1);
        float corr0 = fast_exp2(m0 - mn0), corr1 = fast_exp2(m1 - mn1);
        m0 = mn0; m1 = mn1;

        float rs0 = 0.0f, rs1 = 0.0f;
        int pr0 = (w * 16 + g) * PSTR, pr1 = (w * 16 + g + 8) * PSTR;
#pragma unroll
        for (int nt = 0; nt < 8; nt++) {
            float p00 = fast_exp2(s[nt][0] - mn0);
            float p01 = fast_exp2(s[nt][1] - mn0);
            float p10 = fast_exp2(s[nt][2] - mn1);
            float p11 = fast_exp2(s[nt][3] - mn1);
            rs0 += p00 + p01;
            rs1 += p10 + p11;
            int pc = nt * 8 + 2 * c;
            *(float2*)&Ps[pr0 + pc] = make_float2(__uint_as_float(f2tf(p00)),
                                                  __uint_as_float(f2tf(p01)));
            *(float2*)&Ps[pr1 + pc] = make_float2(__uint_as_float(f2tf(p10)),
                                                  __uint_as_float(f2tf(p11)));
        }
        rs0 += __shfl_xor_sync(0xffffffffu, rs0, 1);
        rs0 += __shfl_xor_sync(0xffffffffu, rs0, 2);
        rs1 += __shfl_xor_sync(0xffffffffu, rs1, 1);
        rs1 += __shfl_xor_sync(0xffffffffu, rs1, 2);
        l0 = l0 * corr0 + rs0;
        l1 = l1 * corr1 + rs1;
#pragma unroll
        for (int nt = 0; nt < 16; nt++) {
            o[nt][0] *= corr0; o[nt][1] *= corr0;
            o[nt][2] *= corr1; o[nt][3] *= corr1;
        }
        __syncwarp();

        // ---- O += P @ V ----
#pragma unroll
        for (int ks = 0; ks < 8; ks++) {
            uint32_t af[4];
            af[0] = __float_as_uint(Ps[pr0 + ks * 8 + c]);
            af[1] = __float_as_uint(Ps[pr1 + ks * 8 + c]);
            af[2] = __float_as_uint(Ps[pr0 + ks * 8 + c + 4]);
            af[3] = __float_as_uint(Ps[pr1 + ks * 8 + c + 4]);
#pragma unroll
            for (int nt = 0; nt < 16; nt++) {
                uint32_t bf[2];
                bf[0] = __float_as_uint(Vs[(ks * 8 + c) * VSTR + nt * 8 + g]);
                bf[1] = __float_as_uint(Vs[(ks * 8 + c + 4) * VSTR + nt * 8 + g]);
                mma_tf32(o[nt], af, bf);
            }
        }
    }

    // ---- epilogue: normalize, store ----
    float inv0 = 1.0f / l0, inv1 = 1.0f / l1;
    size_t r0 = ((size_t)b * SEQ + q0 + w * 16 + g) * DIM;
    size_t r1 = r0 + 8 * DIM;
#pragma unroll
    for (int nt = 0; nt < 16; nt++) {
        int col = nt * 8 + 2 * c;
        *(float2*)&out[r0 + col] = make_float2(o[nt][0] * inv0, o[nt][1] * inv0);
        *(float2*)&out[r1 + col] = make_float2(o[nt][2] * inv1, o[nt][3] * inv1);
    }
}

// ---------------------------------------------------------------------------
extern "C" void kernel_launch(void* const* d_in, const int* in_sizes, int n_in,
                              void* d_out, int out_size) {
    const float* x    = (const float*)d_in[0];
    const float* W    = (const float*)d_in[1];
    const float* bias = (const float*)d_in[2];
    float* out = (float*)d_out;

    dim3 g1(128, 3);
    qkv_mma_kernel<<<g1, 256>>>(x, W, bias);

    cudaFuncSetAttribute(attn_kernel, cudaFuncAttributeMaxDynamicSharedMemorySize,
                         ATTN_SMEM_BYTES);
    dim3 g2(SEQ / 128, BATCH);
    attn_kernel<<<g2, 256, ATTN_SMEM_BYTES>>>(out);
}

// round 4
// speedup vs baseline: 6.7738x; 1.5006x over previous
#include <cuda_runtime.h>
#include <cuda_bf16.h>
#include <cstdint>

#define BATCH 4
#define SEQ   4096
#define DMODEL 1024
#define DIM   128
#define NE    384
#define MTOT  (BATCH * SEQ)   // 16384

// Device-global scratch (no cudaMalloc allowed)
__device__ float g_Q[MTOT * DIM];   // pre-scaled by 128^-0.5*log2(e), tf32-rounded
__device__ float g_K[MTOT * DIM];   // tf32-rounded
__device__ float g_V[MTOT * DIM];   // tf32-rounded
__device__ __nv_bfloat16 g_Xhi[(size_t)MTOT * DMODEL];
__device__ __nv_bfloat16 g_Xlo[(size_t)MTOT * DMODEL];
__device__ __nv_bfloat16 g_Whi[(size_t)NE * DMODEL];   // [n][k] (transposed)
__device__ __nv_bfloat16 g_Wlo[(size_t)NE * DMODEL];

// ---------------------------------------------------------------------------
// helpers
// ---------------------------------------------------------------------------
__device__ __forceinline__ uint32_t f2tf(float x) {
    uint32_t r;
    asm("cvt.rna.tf32.f32 %0, %1;" : "=r"(r) : "f"(x));
    return r;
}

__device__ __forceinline__ void mma_tf32(float* d, const uint32_t* a, const uint32_t* b) {
    asm volatile(
        "mma.sync.aligned.m16n8k8.row.col.f32.tf32.tf32.f32 "
        "{%0,%1,%2,%3}, {%4,%5,%6,%7}, {%8,%9}, {%0,%1,%2,%3};"
        : "+f"(d[0]), "+f"(d[1]), "+f"(d[2]), "+f"(d[3])
        : "r"(a[0]), "r"(a[1]), "r"(a[2]), "r"(a[3]), "r"(b[0]), "r"(b[1]));
}

__device__ __forceinline__ void mma_bf16(float* d, const uint32_t* a, uint32_t b0, uint32_t b1) {
    asm volatile(
        "mma.sync.aligned.m16n8k16.row.col.f32.bf16.bf16.f32 "
        "{%0,%1,%2,%3}, {%4,%5,%6,%7}, {%8,%9}, {%0,%1,%2,%3};"
        : "+f"(d[0]), "+f"(d[1]), "+f"(d[2]), "+f"(d[3])
        : "r"(a[0]), "r"(a[1]), "r"(a[2]), "r"(a[3]), "r"(b0), "r"(b1));
}

__device__ __forceinline__ void cp16(void* smem, const void* gmem) {
    uint32_t s = (uint32_t)__cvta_generic_to_shared(smem);
    asm volatile("cp.async.cg.shared.global [%0], [%1], 16;" :: "r"(s), "l"(gmem));
}
__device__ __forceinline__ void cp_commit() {
    asm volatile("cp.async.commit_group;");
}
__device__ __forceinline__ void cp_wait_all() {
    asm volatile("cp.async.wait_group 0;");
}

// exp2 entirely on the FMA pipe (no MUFU).
__device__ __forceinline__ float fast_exp2(float x) {
    x = fmaxf(x, -126.0f);
    float r = x + 12582912.0f;
    float i = r - 12582912.0f;
    float f = x - i;
    float p = 1.3333558146428443e-3f;
    p = fmaf(p, f, 9.618129107628477e-3f);
    p = fmaf(p, f, 5.5504108664821576e-2f);
    p = fmaf(p, f, 2.402265069591007e-1f);
    p = fmaf(p, f, 6.931471805599453e-1f);
    p = fmaf(p, f, 1.0f);
    float s = __int_as_float((__float_as_int(r) - 0x4B400000 + 127) << 23);
    return p * s;
}

// ---------------------------------------------------------------------------
// Split kernels: x -> Xhi+Xlo (bf16), W -> Whi+Wlo (bf16, transposed [n][k])
// ---------------------------------------------------------------------------
__global__ __launch_bounds__(256)
void split_x_kernel(const float* __restrict__ x) {
    size_t i = (size_t)blockIdx.x * 256 + threadIdx.x;  // one float4
    float4 v = ((const float4*)x)[i];
    __nv_bfloat16 h0 = __float2bfloat16(v.x);
    __nv_bfloat16 h1 = __float2bfloat16(v.y);
    __nv_bfloat16 h2 = __float2bfloat16(v.z);
    __nv_bfloat16 h3 = __float2bfloat16(v.w);
    __nv_bfloat162 hi0; hi0.x = h0; hi0.y = h1;
    __nv_bfloat162 hi1; hi1.x = h2; hi1.y = h3;
    __nv_bfloat162 lo0, lo1;
    lo0.x = __float2bfloat16(v.x - __bfloat162float(h0));
    lo0.y = __float2bfloat16(v.y - __bfloat162float(h1));
    lo1.x = __float2bfloat16(v.z - __bfloat162float(h2));
    lo1.y = __float2bfloat16(v.w - __bfloat162float(h3));
    ((__nv_bfloat162*)g_Xhi)[i * 2]     = hi0;
    ((__nv_bfloat162*)g_Xhi)[i * 2 + 1] = hi1;
    ((__nv_bfloat162*)g_Xlo)[i * 2]     = lo0;
    ((__nv_bfloat162*)g_Xlo)[i * 2 + 1] = lo1;
}

__global__ __launch_bounds__(256)
void split_w_kernel(const float* __restrict__ W) {
    int idx = blockIdx.x * 256 + threadIdx.x;   // over NE*DMODEL
    int n = idx / DMODEL, k = idx - n * DMODEL;
    float v = W[(size_t)k * NE + n];
    __nv_bfloat16 h = __float2bfloat16(v);
    g_Whi[idx] = h;
    g_Wlo[idx] = __float2bfloat16(v - __bfloat162float(h));
}

// ---------------------------------------------------------------------------
// Kernel 1: QKV projection, bf16 3-term split mma (m16n8k16), cp.async
// double-buffered. BM=128 BN=128 BK=32. 8 warps 4(m)x2(n), warp 32x64.
// Epilogue: +bias, de-interleave, pre-scale Q, tf32-round all of Q/K/V.
// ---------------------------------------------------------------------------
#define QASTR 40   // bf16 units per row (32 + 8 pad)
#define QKV_SMEM ((2 * 2 * 128 * QASTR + 2 * 2 * 128 * QASTR) * 2)  // 81920 B

__global__ __launch_bounds__(256)
void qkv_mma_kernel(const float* __restrict__ bias) {
    extern __shared__ __nv_bfloat16 qsm[];
    __nv_bfloat16* Ahi = qsm;                       // [2][128*40]
    __nv_bfloat16* Alo = Ahi + 2 * 128 * QASTR;
    __nv_bfloat16* Bhi = Alo + 2 * 128 * QASTR;
    __nv_bfloat16* Blo = Bhi + 2 * 128 * QASTR;

    const int row0 = blockIdx.x * 128;
    const int col0 = blockIdx.y * 128;
    const int tid = threadIdx.x;
    const int w = tid >> 5, lane = tid & 31;
    const int g = lane >> 2, c = lane & 3;
    const int wm = w >> 1, wn = w & 1;

    float acc[2][8][4];
#pragma unroll
    for (int mt = 0; mt < 2; mt++)
#pragma unroll
        for (int nt = 0; nt < 8; nt++)
#pragma unroll
            for (int j = 0; j < 4; j++) acc[mt][nt][j] = 0.0f;

    // prefetch tile 0 into buffer 0
#pragma unroll
    for (int it2 = 0; it2 < 2; it2++) {
        int slot = tid + it2 * 256;
        int r = slot >> 2, sg = (slot & 3) * 8;
        cp16(Ahi + r * QASTR + sg, g_Xhi + (size_t)(row0 + r) * DMODEL + sg);
        cp16(Alo + r * QASTR + sg, g_Xlo + (size_t)(row0 + r) * DMODEL + sg);
        cp16(Bhi + r * QASTR + sg, g_Whi + (size_t)(col0 + r) * DMODEL + sg);
        cp16(Blo + r * QASTR + sg, g_Wlo + (size_t)(col0 + r) * DMODEL + sg);
    }
    cp_commit();

    for (int t = 0; t < 32; t++) {          // 32 tiles x BK=32 = DMODEL
        cp_wait_all();
        __syncthreads();
        if (t < 31) {
            int k0 = (t + 1) * 32;
            int bo = ((t + 1) & 1) * 128 * QASTR;
#pragma unroll
            for (int it2 = 0; it2 < 2; it2++) {
                int slot = tid + it2 * 256;
                int r = slot >> 2, sg = (slot & 3) * 8;
                cp16(Ahi + bo + r * QASTR + sg, g_Xhi + (size_t)(row0 + r) * DMODEL + k0 + sg);
                cp16(Alo + bo + r * QASTR + sg, g_Xlo + (size_t)(row0 + r) * DMODEL + k0 + sg);
                cp16(Bhi + bo + r * QASTR + sg, g_Whi + (size_t)(col0 + r) * DMODEL + k0 + sg);
                cp16(Blo + bo + r * QASTR + sg, g_Wlo + (size_t)(col0 + r) * DMODEL + k0 + sg);
            }
            cp_commit();
        }

        const __nv_bfloat16* pAh = Ahi + (t & 1) * 128 * QASTR;
        const __nv_bfloat16* pAl = Alo + (t & 1) * 128 * QASTR;
        const __nv_bfloat16* pBh = Bhi + (t & 1) * 128 * QASTR;
        const __nv_bfloat16* pBl = Blo + (t & 1) * 128 * QASTR;

#pragma unroll
        for (int ks = 0; ks < 2; ks++) {
            uint32_t ah[2][4], al[2][4];
#pragma unroll
            for (int mt = 0; mt < 2; mt++) {
                int ar = wm * 32 + mt * 16 + g;
                const __nv_bfloat16* p = pAh + ar * QASTR + ks * 16 + 2 * c;
                ah[mt][0] = *(const uint32_t*)p;
                ah[mt][1] = *(const uint32_t*)(p + 8 * QASTR);
                ah[mt][2] = *(const uint32_t*)(p + 8);
                ah[mt][3] = *(const uint32_t*)(p + 8 * QASTR + 8);
                const __nv_bfloat16* q = pAl + ar * QASTR + ks * 16 + 2 * c;
                al[mt][0] = *(const uint32_t*)q;
                al[mt][1] = *(const uint32_t*)(q + 8 * QASTR);
                al[mt][2] = *(const uint32_t*)(q + 8);
                al[mt][3] = *(const uint32_t*)(q + 8 * QASTR + 8);
            }
#pragma unroll
            for (int nt = 0; nt < 8; nt++) {
                int bc = wn * 64 + nt * 8 + g;
                const __nv_bfloat16* pb = pBh + bc * QASTR + ks * 16 + 2 * c;
                uint32_t bh0 = *(const uint32_t*)pb;
                uint32_t bh1 = *(const uint32_t*)(pb + 8);
                const __nv_bfloat16* pl = pBl + bc * QASTR + ks * 16 + 2 * c;
                uint32_t bl0 = *(const uint32_t*)pl;
                uint32_t bl1 = *(const uint32_t*)(pl + 8);
#pragma unroll
                for (int mt = 0; mt < 2; mt++) {
                    mma_bf16(acc[mt][nt], ah[mt], bh0, bh1);
                    mma_bf16(acc[mt][nt], al[mt], bh0, bh1);
                    mma_bf16(acc[mt][nt], ah[mt], bl0, bl1);
                }
            }
        }
    }

    // Epilogue: bias + de-interleave + tf32-round (+ Q pre-scale)
    const float pre = 0.12751745f;  // 128^-0.5 * log2(e)
#pragma unroll
    for (int mt = 0; mt < 2; mt++) {
#pragma unroll
        for (int nt = 0; nt < 8; nt++) {
            int er = row0 + wm * 32 + mt * 16 + g;
            int ec = col0 + wn * 64 + nt * 8 + 2 * c;
#pragma unroll
            for (int j = 0; j < 4; j++) {
                int r = er + ((j >= 2) ? 8 : 0);
                int e = ec + (j & 1);
                float v = acc[mt][nt][j] + bias[e];
                int d = e / 3, wh = e - 3 * d;
                if (wh == 0)
                    g_Q[(size_t)r * DIM + d] = __uint_as_float(f2tf(v * pre));
                else if (wh == 1)
                    g_K[(size_t)r * DIM + d] = __uint_as_float(f2tf(v));
                else
                    g_V[(size_t)r * DIM + d] = __uint_as_float(f2tf(v));
            }
        }
    }
}

// ---------------------------------------------------------------------------
// Kernel 2: flash attention, tf32 mma.sync, cp.async double-buffered K/V
// (pre-converted to tf32 bits by QKV epilogue -> zero conversion here).
// Block = 128 queries x one batch, 8 warps x 16 q-rows each.
// NT = SEQ/64 = 64 key tiles  (round-3 bug: was 32 -> attended half the keys)
// ---------------------------------------------------------------------------
#define KSTR 132
#define VSTR 136
#define PSTR 68
#define NT   (SEQ / 64)
#define ATTN_SMEM ((2 * 64 * KSTR + 2 * 64 * VSTR + 128 * PSTR) * 4)  // 172032 B

__global__ __launch_bounds__(256, 1)
void attn_kernel(float* __restrict__ out) {
    extern __shared__ float sm[];
    float* Ksb = sm;                       // [2][64*KSTR]
    float* Vsb = Ksb + 2 * 64 * KSTR;      // [2][64*VSTR]
    float* Ps  = Vsb + 2 * 64 * VSTR;      // [128][PSTR]

    const int b  = blockIdx.y;
    const int q0 = blockIdx.x * 128;
    const int tid = threadIdx.x;
    const int w = tid >> 5, lane = tid & 31;
    const int g = lane >> 2, c = lane & 3;

    const float* Qg = g_Q + (size_t)b * SEQ * DIM;
    const float* Kg = g_K + (size_t)b * SEQ * DIM;
    const float* Vg = g_V + (size_t)b * SEQ * DIM;

    // Q fragments (already pre-scaled + tf32-rounded)
    uint32_t qf[16][4];
    {
        size_t qr = (size_t)(q0 + w * 16 + g) * DIM;
#pragma unroll
        for (int ks = 0; ks < 16; ks++) {
            qf[ks][0] = __float_as_uint(Qg[qr + ks * 8 + c]);
            qf[ks][1] = __float_as_uint(Qg[qr + 8 * DIM + ks * 8 + c]);
            qf[ks][2] = __float_as_uint(Qg[qr + ks * 8 + c + 4]);
            qf[ks][3] = __float_as_uint(Qg[qr + 8 * DIM + ks * 8 + c + 4]);
        }
    }

    float o[16][4];
#pragma unroll
    for (int nt = 0; nt < 16; nt++)
#pragma unroll
        for (int j = 0; j < 4; j++) o[nt][j] = 0.0f;
    float m0 = -1e30f, m1 = -1e30f, l0 = 0.0f, l1 = 0.0f;

    // prefetch tile 0
#pragma unroll
    for (int i = 0; i < 8; i++) {
        int slot = tid + i * 256;
        int r = slot >> 5, cc = (slot & 31) * 4;
        cp16(Ksb + r * KSTR + cc, Kg + (size_t)r * DIM + cc);
        cp16(Vsb + r * VSTR + cc, Vg + (size_t)r * DIM + cc);
    }
    cp_commit();

    for (int t = 0; t < NT; t++) {
        cp_wait_all();
        __syncthreads();
        if (t < NT - 1) {
            int k0 = (t + 1) * 64;
            int kb = ((t + 1) & 1) * 64 * KSTR;
            int vb = ((t + 1) & 1) * 64 * VSTR;
#pragma unroll
            for (int i = 0; i < 8; i++) {
                int slot = tid + i * 256;
                int r = slot >> 5, cc = (slot & 31) * 4;
                cp16(Ksb + kb + r * KSTR + cc, Kg + (size_t)(k0 + r) * DIM + cc);
                cp16(Vsb + vb + r * VSTR + cc, Vg + (size_t)(k0 + r) * DIM + cc);
            }
            cp_commit();
        }

        const float* Ks = Ksb + (t & 1) * 64 * KSTR;
        const float* Vs = Vsb + (t & 1) * 64 * VSTR;

        // ---- S = Q @ K^T (log2 domain) ----
        float s[8][4];
#pragma unroll
        for (int nt = 0; nt < 8; nt++) {
            s[nt][0] = 0.0f; s[nt][1] = 0.0f; s[nt][2] = 0.0f; s[nt][3] = 0.0f;
#pragma unroll
            for (int ks = 0; ks < 16; ks++) {
                uint32_t bf[2];
                bf[0] = __float_as_uint(Ks[(nt * 8 + g) * KSTR + ks * 8 + c]);
                bf[1] = __float_as_uint(Ks[(nt * 8 + g) * KSTR + ks * 8 + c + 4]);
                mma_tf32(s[nt], qf[ks], bf);
            }
        }

        // ---- online softmax ----
        float rmax0 = -1e30f, rmax1 = -1e30f;
#pragma unroll
        for (int nt = 0; nt < 8; nt++) {
            rmax0 = fmaxf(rmax0, fmaxf(s[nt][0], s[nt][1]));
            rmax1 = fmaxf(rmax1, fmaxf(s[nt][2], s[nt][3]));
        }
        rmax0 = fmaxf(rmax0, __shfl_xor_sync(0xffffffffu, rmax0, 1));
        rmax0 = fmaxf(rmax0, __shfl_xor_sync(0xffffffffu, rmax0, 2));
        rmax1 = fmaxf(rmax1, __shfl_xor_sync(0xffffffffu, rmax1, 1));
        rmax1 = fmaxf(rmax1, __shfl_xor_sync(0xffffffffu, rmax1, 2));

        float mn0 = fmaxf(m0, rmax0), mn1 = fmaxf(m1, rmax1);
        float corr0 = fast_exp2(m0 - mn0), corr1 = fast_exp2(m1 - mn1);
        m0 = mn0; m1 = mn1;

        float rs0 = 0.0f, rs1 = 0.0f;
        int pr0 = (w * 16 + g) * PSTR, pr1 = (w * 16 + g + 8) * PSTR;
#pragma unroll
        for (int nt = 0; nt < 8; nt++) {
            float p00 = fast_exp2(s[nt][0] - mn0);
            float p01 = fast_exp2(s[nt][1] - mn0);
            float p10 = fast_exp2(s[nt][2] - mn1);
            float p11 = fast_exp2(s[nt][3] - mn1);
            rs0 += p00 + p01;
            rs1 += p10 + p11;
            int pc = nt * 8 + 2 * c;
            *(float2*)&Ps[pr0 + pc] = make_float2(__uint_as_float(f2tf(p00)),
                                                  __uint_as_float(f2tf(p01)));
            *(float2*)&Ps[pr1 + pc] = make_float2(__uint_as_float(f2tf(p10)),
                                                  __uint_as_float(f2tf(p11)));
        }
        rs0 += __shfl_xor_sync(0xffffffffu, rs0, 1);
        rs0 += __shfl_xor_sync(0xffffffffu, rs0, 2);
        rs1 += __shfl_xor_sync(0xffffffffu, rs1, 1);
        rs1 += __shfl_xor_sync(0xffffffffu, rs1, 2);
        l0 = l0 * corr0 + rs0;
        l1 = l1 * corr1 + rs1;
#pragma unroll
        for (int nt = 0; nt < 16; nt++) {
            o[nt][0] *= corr0; o[nt][1] *= corr0;
            o[nt][2] *= corr1; o[nt][3] *= corr1;
        }
        __syncwarp();

        // ---- O += P @ V ----
#pragma unroll
        for (int ks = 0; ks < 8; ks++) {
            uint32_t af[4];
            af[0] = __float_as_uint(Ps[pr0 + ks * 8 + c]);
            af[1] = __float_as_uint(Ps[pr1 + ks * 8 + c]);
            af[2] = __float_as_uint(Ps[pr0 + ks * 8 + c + 4]);
            af[3] = __float_as_uint(Ps[pr1 + ks * 8 + c + 4]);
#pragma unroll
            for (int nt = 0; nt < 16; nt++) {
                uint32_t bf[2];
                bf[0] = __float_as_uint(Vs[(ks * 8 + c) * VSTR + nt * 8 + g]);
                bf[1] = __float_as_uint(Vs[(ks * 8 + c + 4) * VSTR + nt * 8 + g]);
                mma_tf32(o[nt], af, bf);
            }
        }
    }

    // ---- epilogue ----
    float inv0 = 1.0f / l0, inv1 = 1.0f / l1;
    size_t r0 = ((size_t)b * SEQ + q0 + w * 16 + g) * DIM;
    size_t r1 = r0 + 8 * DIM;
#pragma unroll
    for (int nt = 0; nt < 16; nt++) {
        int col = nt * 8 + 2 * c;
        *(float2*)&out[r0 + col] = make_float2(o[nt][0] * inv0, o[nt][1] * inv0);
        *(float2*)&out[r1 + col] = make_float2(o[nt][2] * inv1, o[nt][3] * inv1);
    }
}

// ---------------------------------------------------------------------------
extern "C" void kernel_launch(void* const* d_in, const int* in_sizes, int n_in,
                              void* d_out, int out_size) {
    const float* x    = (const float*)d_in[0];
    const float* W    = (const float*)d_in[1];
    const float* bias = (const float*)d_in[2];
    float* out = (float*)d_out;

    split_x_kernel<<<(MTOT * DMODEL / 4) / 256, 256>>>(x);
    split_w_kernel<<<(NE * DMODEL) / 256, 256>>>(W);

    cudaFuncSetAttribute(qkv_mma_kernel, cudaFuncAttributeMaxDynamicSharedMemorySize,
                         QKV_SMEM);
    dim3 g1(128, 3);
    qkv_mma_kernel<<<g1, 256, QKV_SMEM>>>(bias);

    cudaFuncSetAttribute(attn_kernel, cudaFuncAttributeMaxDynamicSharedMemorySize,
                         ATTN_SMEM);
    dim3 g2(SEQ / 128, BATCH);
    attn_kernel<<<g2, 256, ATTN_SMEM>>>(out);
}

// round 5
// speedup vs baseline: 9.5086x; 1.4037x over previous
#include <cuda_runtime.h>
#include <cuda_bf16.h>
#include <cuda_fp16.h>
#include <cstdint>

#define BATCH 4
#define SEQ   4096
#define DMODEL 1024
#define DIM   128
#define NE    384
#define MTOT  (BATCH * SEQ)   // 16384

// Device-global scratch (no cudaMalloc allowed)
// fp16, fragment-interleaved layouts (see perm16 below)
__device__ __half g_Qh[MTOT * DIM];                  // pre-scaled, dim-interleaved
__device__ __half g_Kh[MTOT * DIM];                  // dim-interleaved
__device__ __half g_Vth[(size_t)BATCH * DIM * SEQ];  // transposed [b][d][t], key-interleaved
__device__ __nv_bfloat16 g_Xhi[(size_t)MTOT * DMODEL];
__device__ __nv_bfloat16 g_Xlo[(size_t)MTOT * DMODEL];
__device__ __nv_bfloat16 g_Whi[(size_t)NE * DMODEL];   // [n][k] (transposed)
__device__ __nv_bfloat16 g_Wlo[(size_t)NE * DMODEL];

// ---------------------------------------------------------------------------
// helpers
// ---------------------------------------------------------------------------
// Interleave within 16-element groups so that mma fragment pairs (p, p+4)
// of 2-element units become adjacent: element j -> (j&~15) | pos(pair)*2 | (j&1)
__device__ __forceinline__ int perm16(int j) {
    int p = (j >> 1) & 7;
    int pos = ((p & 3) << 1) | ((p >> 2) & 1);
    return (j & ~15) | (pos << 1) | (j & 1);
}

__device__ __forceinline__ void mma_f16(float* d, const uint32_t* a, uint32_t b0, uint32_t b1) {
    asm volatile(
        "mma.sync.aligned.m16n8k16.row.col.f32.f16.f16.f32 "
        "{%0,%1,%2,%3}, {%4,%5,%6,%7}, {%8,%9}, {%0,%1,%2,%3};"
        : "+f"(d[0]), "+f"(d[1]), "+f"(d[2]), "+f"(d[3])
        : "r"(a[0]), "r"(a[1]), "r"(a[2]), "r"(a[3]), "r"(b0), "r"(b1));
}

__device__ __forceinline__ void mma_bf16(float* d, const uint32_t* a, uint32_t b0, uint32_t b1) {
    asm volatile(
        "mma.sync.aligned.m16n8k16.row.col.f32.bf16.bf16.f32 "
        "{%0,%1,%2,%3}, {%4,%5,%6,%7}, {%8,%9}, {%0,%1,%2,%3};"
        : "+f"(d[0]), "+f"(d[1]), "+f"(d[2]), "+f"(d[3])
        : "r"(a[0]), "r"(a[1]), "r"(a[2]), "r"(a[3]), "r"(b0), "r"(b1));
}

__device__ __forceinline__ void cp16(void* smem, const void* gmem) {
    uint32_t s = (uint32_t)__cvta_generic_to_shared(smem);
    asm volatile("cp.async.cg.shared.global [%0], [%1], 16;" :: "r"(s), "l"(gmem));
}
__device__ __forceinline__ void cp_commit() {
    asm volatile("cp.async.commit_group;");
}
__device__ __forceinline__ void cp_wait_all() {
    asm volatile("cp.async.wait_group 0;");
}

// exp2 entirely on the FMA pipe (no MUFU).
__device__ __forceinline__ float fast_exp2(float x) {
    x = fmaxf(x, -126.0f);
    float r = x + 12582912.0f;
    float i = r - 12582912.0f;
    float f = x - i;
    float p = 1.3333558146428443e-3f;
    p = fmaf(p, f, 9.618129107628477e-3f);
    p = fmaf(p, f, 5.5504108664821576e-2f);
    p = fmaf(p, f, 2.402265069591007e-1f);
    p = fmaf(p, f, 6.931471805599453e-1f);
    p = fmaf(p, f, 1.0f);
    float s = __int_as_float((__float_as_int(r) - 0x4B400000 + 127) << 23);
    return p * s;
}

// ---------------------------------------------------------------------------
// Split kernels: x -> Xhi+Xlo (bf16), W -> Whi+Wlo (bf16, transposed [n][k])
// ---------------------------------------------------------------------------
__global__ __launch_bounds__(256)
void split_x_kernel(const float* __restrict__ x) {
    size_t i = (size_t)blockIdx.x * 256 + threadIdx.x;  // one float4
    float4 v = ((const float4*)x)[i];
    __nv_bfloat16 h0 = __float2bfloat16(v.x);
    __nv_bfloat16 h1 = __float2bfloat16(v.y);
    __nv_bfloat16 h2 = __float2bfloat16(v.z);
    __nv_bfloat16 h3 = __float2bfloat16(v.w);
    __nv_bfloat162 hi0; hi0.x = h0; hi0.y = h1;
    __nv_bfloat162 hi1; hi1.x = h2; hi1.y = h3;
    __nv_bfloat162 lo0, lo1;
    lo0.x = __float2bfloat16(v.x - __bfloat162float(h0));
    lo0.y = __float2bfloat16(v.y - __bfloat162float(h1));
    lo1.x = __float2bfloat16(v.z - __bfloat162float(h2));
    lo1.y = __float2bfloat16(v.w - __bfloat162float(h3));
    ((__nv_bfloat162*)g_Xhi)[i * 2]     = hi0;
    ((__nv_bfloat162*)g_Xhi)[i * 2 + 1] = hi1;
    ((__nv_bfloat162*)g_Xlo)[i * 2]     = lo0;
    ((__nv_bfloat162*)g_Xlo)[i * 2 + 1] = lo1;
}

__global__ __launch_bounds__(256)
void split_w_kernel(const float* __restrict__ W) {
    int idx = blockIdx.x * 256 + threadIdx.x;   // over NE*DMODEL
    int n = idx / DMODEL, k = idx - n * DMODEL;
    float v = W[(size_t)k * NE + n];
    __nv_bfloat16 h = __float2bfloat16(v);
    g_Whi[idx] = h;
    g_Wlo[idx] = __float2bfloat16(v - __bfloat162float(h));
}

// ---------------------------------------------------------------------------
// Kernel 1: QKV projection, bf16 3-term split mma (m16n8k16), cp.async
// double-buffered. BM=128 BN=128 BK=32. 8 warps 4(m)x2(n), warp 32x64.
// Epilogue: +bias, de-interleave, write fp16 fragment-interleaved Q/K/Vt.
// ---------------------------------------------------------------------------
#define QASTR 40   // bf16 units per row (32 + 8 pad)
#define QKV_SMEM ((2 * 2 * 128 * QASTR + 2 * 2 * 128 * QASTR) * 2)  // 81920 B

__global__ __launch_bounds__(256)
void qkv_mma_kernel(const float* __restrict__ bias) {
    extern __shared__ __nv_bfloat16 qsm[];
    __nv_bfloat16* Ahi = qsm;                       // [2][128*40]
    __nv_bfloat16* Alo = Ahi + 2 * 128 * QASTR;
    __nv_bfloat16* Bhi = Alo + 2 * 128 * QASTR;
    __nv_bfloat16* Blo = Bhi + 2 * 128 * QASTR;

    const int row0 = blockIdx.x * 128;
    const int col0 = blockIdx.y * 128;
    const int tid = threadIdx.x;
    const int w = tid >> 5, lane = tid & 31;
    const int g = lane >> 2, c = lane & 3;
    const int wm = w >> 1, wn = w & 1;

    float acc[2][8][4];
#pragma unroll
    for (int mt = 0; mt < 2; mt++)
#pragma unroll
        for (int nt = 0; nt < 8; nt++)
#pragma unroll
            for (int j = 0; j < 4; j++) acc[mt][nt][j] = 0.0f;

    // prefetch tile 0 into buffer 0
#pragma unroll
    for (int it2 = 0; it2 < 2; it2++) {
        int slot = tid + it2 * 256;
        int r = slot >> 2, sg = (slot & 3) * 8;
        cp16(Ahi + r * QASTR + sg, g_Xhi + (size_t)(row0 + r) * DMODEL + sg);
        cp16(Alo + r * QASTR + sg, g_Xlo + (size_t)(row0 + r) * DMODEL + sg);
        cp16(Bhi + r * QASTR + sg, g_Whi + (size_t)(col0 + r) * DMODEL + sg);
        cp16(Blo + r * QASTR + sg, g_Wlo + (size_t)(col0 + r) * DMODEL + sg);
    }
    cp_commit();

    for (int t = 0; t < 32; t++) {          // 32 tiles x BK=32 = DMODEL
        cp_wait_all();
        __syncthreads();
        if (t < 31) {
            int k0 = (t + 1) * 32;
            int bo = ((t + 1) & 1) * 128 * QASTR;
#pragma unroll
            for (int it2 = 0; it2 < 2; it2++) {
                int slot = tid + it2 * 256;
                int r = slot >> 2, sg = (slot & 3) * 8;
                cp16(Ahi + bo + r * QASTR + sg, g_Xhi + (size_t)(row0 + r) * DMODEL + k0 + sg);
                cp16(Alo + bo + r * QASTR + sg, g_Xlo + (size_t)(row0 + r) * DMODEL + k0 + sg);
                cp16(Bhi + bo + r * QASTR + sg, g_Whi + (size_t)(col0 + r) * DMODEL + k0 + sg);
                cp16(Blo + bo + r * QASTR + sg, g_Wlo + (size_t)(col0 + r) * DMODEL + k0 + sg);
            }
            cp_commit();
        }

        const __nv_bfloat16* pAh = Ahi + (t & 1) * 128 * QASTR;
        const __nv_bfloat16* pAl = Alo + (t & 1) * 128 * QASTR;
        const __nv_bfloat16* pBh = Bhi + (t & 1) * 128 * QASTR;
        const __nv_bfloat16* pBl = Blo + (t & 1) * 128 * QASTR;

#pragma unroll
        for (int ks = 0; ks < 2; ks++) {
            uint32_t ah[2][4], al[2][4];
#pragma unroll
            for (int mt = 0; mt < 2; mt++) {
                int ar = wm * 32 + mt * 16 + g;
                const __nv_bfloat16* p = pAh + ar * QASTR + ks * 16 + 2 * c;
                ah[mt][0] = *(const uint32_t*)p;
                ah[mt][1] = *(const uint32_t*)(p + 8 * QASTR);
                ah[mt][2] = *(const uint32_t*)(p + 8);
                ah[mt][3] = *(const uint32_t*)(p + 8 * QASTR + 8);
                const __nv_bfloat16* q = pAl + ar * QASTR + ks * 16 + 2 * c;
                al[mt][0] = *(const uint32_t*)q;
                al[mt][1] = *(const uint32_t*)(q + 8 * QASTR);
                al[mt][2] = *(const uint32_t*)(q + 8);
                al[mt][3] = *(const uint32_t*)(q + 8 * QASTR + 8);
            }
#pragma unroll
            for (int nt = 0; nt < 8; nt++) {
                int bc = wn * 64 + nt * 8 + g;
                const __nv_bfloat16* pb = pBh + bc * QASTR + ks * 16 + 2 * c;
                uint32_t bh0 = *(const uint32_t*)pb;
                uint32_t bh1 = *(const uint32_t*)(pb + 8);
                const __nv_bfloat16* pl = pBl + bc * QASTR + ks * 16 + 2 * c;
                uint32_t bl0 = *(const uint32_t*)pl;
                uint32_t bl1 = *(const uint32_t*)(pl + 8);
#pragma unroll
                for (int mt = 0; mt < 2; mt++) {
                    mma_bf16(acc[mt][nt], ah[mt], bh0, bh1);
                    mma_bf16(acc[mt][nt], al[mt], bh0, bh1);
                    mma_bf16(acc[mt][nt], ah[mt], bl0, bl1);
                }
            }
        }
    }

    // Epilogue: bias + de-interleave + fp16 convert into fragment layouts
    const float pre = 0.12751745f;  // 128^-0.5 * log2(e)
#pragma unroll
    for (int mt = 0; mt < 2; mt++) {
#pragma unroll
        for (int nt = 0; nt < 8; nt++) {
            int er = row0 + wm * 32 + mt * 16 + g;
            int ec = col0 + wn * 64 + nt * 8 + 2 * c;
#pragma unroll
            for (int j = 0; j < 4; j++) {
                int r = er + ((j >= 2) ? 8 : 0);
                int e = ec + (j & 1);
                float v = acc[mt][nt][j] + bias[e];
                int d = e / 3, wh = e - 3 * d;
                if (wh == 0) {
                    g_Qh[(size_t)r * DIM + perm16(d)] = __float2half_rn(v * pre);
                } else if (wh == 1) {
                    g_Kh[(size_t)r * DIM + perm16(d)] = __float2half_rn(v);
                } else {
                    int b = r >> 12, tt = r & (SEQ - 1);
                    g_Vth[((size_t)b * DIM + d) * SEQ + perm16(tt)] = __float2half_rn(v);
                }
            }
        }
    }
}

// ---------------------------------------------------------------------------
// Kernel 2: flash attention, fp16 mma (m16n8k16), cp.async double-buffered.
// Block = 128 queries x one batch, 8 warps x 16 q-rows each. 64-key tiles.
// All fragment loads are conflict-free LDS.64 thanks to perm16 layouts.
// ---------------------------------------------------------------------------
#define KSTRH 144   // fp16 units per K smem row (128 + 16)
#define VSTRH 80    // fp16 units per Vt smem row (64 + 16)
#define PSTRH 80
#define NTILES (SEQ / 64)
#define ATTN_SMEM (2*64*KSTRH*2 + 2*128*VSTRH*2 + 128*PSTRH*2)  // 98304 B

__global__ __launch_bounds__(256, 1)
void attn_kernel(float* __restrict__ out) {
    extern __shared__ char asm_[];
    __half* Ksb = (__half*)asm_;                 // [2][64*KSTRH]
    __half* Vtb = Ksb + 2 * 64 * KSTRH;          // [2][128*VSTRH]
    __half* Ps  = Vtb + 2 * 128 * VSTRH;         // [128][PSTRH]

    const int b  = blockIdx.y;
    const int q0 = blockIdx.x * 128;
    const int tid = threadIdx.x;
    const int w = tid >> 5, lane = tid & 31;
    const int g = lane >> 2, c = lane & 3;

    const __half* Qg = g_Qh + (size_t)b * SEQ * DIM;
    const __half* Kg = g_Kh + (size_t)b * SEQ * DIM;
    const __half* Vg = g_Vth + (size_t)b * DIM * SEQ;

    // Q fragments: 8 k-steps (k16) x 4 regs. Layout already interleaved:
    // uint2 at ks*16 + 4c gives (pair c, pair c+4) = (a0,a2); row+8 -> (a1,a3)
    uint32_t qf[8][4];
    {
        size_t qr = (size_t)(q0 + w * 16 + g) * DIM;
#pragma unroll
        for (int ks = 0; ks < 8; ks++) {
            uint2 t0 = *(const uint2*)(Qg + qr + ks * 16 + 4 * c);
            uint2 t1 = *(const uint2*)(Qg + qr + 8 * DIM + ks * 16 + 4 * c);
            qf[ks][0] = t0.x; qf[ks][2] = t0.y;
            qf[ks][1] = t1.x; qf[ks][3] = t1.y;
        }
    }

    float o[16][4];
#pragma unroll
    for (int nt = 0; nt < 16; nt++)
#pragma unroll
        for (int j = 0; j < 4; j++) o[nt][j] = 0.0f;
    float m0 = -1e30f, m1 = -1e30f, l0 = 0.0f, l1 = 0.0f;

    // prefetch tile 0: K 64x128h (16 cp16/row), Vt 128x64h (8 cp16/row)
#pragma unroll
    for (int i = 0; i < 4; i++) {
        int slot = tid + i * 256;
        int r = slot >> 4, cc = (slot & 15) * 8;
        cp16(Ksb + r * KSTRH + cc, Kg + (size_t)r * DIM + cc);
    }
#pragma unroll
    for (int i = 0; i < 4; i++) {
        int slot = tid + i * 256;
        int r = slot >> 3, cc = (slot & 7) * 8;
        cp16(Vtb + r * VSTRH + cc, Vg + (size_t)r * SEQ + cc);
    }
    cp_commit();

    for (int t = 0; t < NTILES; t++) {
        cp_wait_all();
        __syncthreads();
        if (t < NTILES - 1) {
            int k0 = (t + 1) * 64;
            int kb = ((t + 1) & 1) * 64 * KSTRH;
            int vb = ((t + 1) & 1) * 128 * VSTRH;
#pragma unroll
            for (int i = 0; i < 4; i++) {
                int slot = tid + i * 256;
                int r = slot >> 4, cc = (slot & 15) * 8;
                cp16(Ksb + kb + r * KSTRH + cc, Kg + (size_t)(k0 + r) * DIM + cc);
            }
#pragma unroll
            for (int i = 0; i < 4; i++) {
                int slot = tid + i * 256;
                int r = slot >> 3, cc = (slot & 7) * 8;
                cp16(Vtb + vb + r * VSTRH + cc, Vg + (size_t)r * SEQ + k0 + cc);
            }
            cp_commit();
        }

        const __half* Ks = Ksb + (t & 1) * 64 * KSTRH;
        const __half* Vt = Vtb + (t & 1) * 128 * VSTRH;

        // ---- S = Q @ K^T (log2 domain; Q pre-scaled) ----
        float s[8][4];
#pragma unroll
        for (int nt = 0; nt < 8; nt++) {
            s[nt][0] = 0.0f; s[nt][1] = 0.0f; s[nt][2] = 0.0f; s[nt][3] = 0.0f;
#pragma unroll
            for (int ks = 0; ks < 8; ks++) {
                uint2 bb = *(const uint2*)(Ks + (nt * 8 + g) * KSTRH + ks * 16 + 4 * c);
                mma_f16(s[nt], qf[ks], bb.x, bb.y);
            }
        }

        // ---- online softmax (rows g, g+8 of warp's 16) ----
        float rmax0 = -1e30f, rmax1 = -1e30f;
#pragma unroll
        for (int nt = 0; nt < 8; nt++) {
            rmax0 = fmaxf(rmax0, fmaxf(s[nt][0], s[nt][1]));
            rmax1 = fmaxf(rmax1, fmaxf(s[nt][2], s[nt][3]));
        }
        rmax0 = fmaxf(rmax0, __shfl_xor_sync(0xffffffffu, rmax0, 1));
        rmax0 = fmaxf(rmax0, __shfl_xor_sync(0xffffffffu, rmax0, 2));
        rmax1 = fmaxf(rmax1, __shfl_xor_sync(0xffffffffu, rmax1, 1));
        rmax1 = fmaxf(rmax1, __shfl_xor_sync(0xffffffffu, rmax1, 2));

        float mn0 = fmaxf(m0, rmax0), mn1 = fmaxf(m1, rmax1);
        float corr0 = fast_exp2(m0 - mn0), corr1 = fast_exp2(m1 - mn1);
        m0 = mn0; m1 = mn1;

        float rs0 = 0.0f, rs1 = 0.0f;
        const int pr0 = (w * 16 + g) * PSTRH;
        const int pr1 = pr0 + 8 * PSTRH;
#pragma unroll
        for (int nt = 0; nt < 8; nt++) {
            float p00 = fast_exp2(s[nt][0] - mn0);
            float p01 = fast_exp2(s[nt][1] - mn0);
            float p10 = fast_exp2(s[nt][2] - mn1);
            float p11 = fast_exp2(s[nt][3] - mn1);
            rs0 += p00 + p01;
            rs1 += p10 + p11;
            // store P fp16 pair at interleaved key position
            int group = nt >> 1;
            int p8 = (nt & 1) * 4 + c;
            int pos = ((p8 & 3) << 1) | (p8 >> 2);
            int off = group * 16 + pos * 2;
            *(__half2*)(Ps + pr0 + off) = __floats2half2_rn(p00, p01);
            *(__half2*)(Ps + pr1 + off) = __floats2half2_rn(p10, p11);
        }
        rs0 += __shfl_xor_sync(0xffffffffu, rs0, 1);
        rs0 += __shfl_xor_sync(0xffffffffu, rs0, 2);
        rs1 += __shfl_xor_sync(0xffffffffu, rs1, 1);
        rs1 += __shfl_xor_sync(0xffffffffu, rs1, 2);
        l0 = l0 * corr0 + rs0;
        l1 = l1 * corr1 + rs1;
#pragma unroll
        for (int nt = 0; nt < 16; nt++) {
            o[nt][0] *= corr0; o[nt][1] *= corr0;
            o[nt][2] *= corr1; o[nt][3] *= corr1;
        }
        __syncwarp();

        // ---- O += P @ V : 4 k16 steps over 64 keys ----
#pragma unroll
        for (int ksp = 0; ksp < 4; ksp++) {
            uint2 a02 = *(const uint2*)(Ps + pr0 + ksp * 16 + 4 * c);
            uint2 a13 = *(const uint2*)(Ps + pr1 + ksp * 16 + 4 * c);
            uint32_t af[4] = {a02.x, a13.x, a02.y, a13.y};
#pragma unroll
            for (int nt = 0; nt < 16; nt++) {
                uint2 bb = *(const uint2*)(Vt + (nt * 8 + g) * VSTRH + ksp * 16 + 4 * c);
                mma_f16(o[nt], af, bb.x, bb.y);
            }
        }
    }

    // ---- epilogue: normalize, store ----
    float inv0 = 1.0f / l0, inv1 = 1.0f / l1;
    size_t r0 = ((size_t)b * SEQ + q0 + w * 16 + g) * DIM;
    size_t r1 = r0 + 8 * DIM;
#pragma unroll
    for (int nt = 0; nt < 16; nt++) {
        int col = nt * 8 + 2 * c;
        *(float2*)&out[r0 + col] = make_float2(o[nt][0] * inv0, o[nt][1] * inv0);
        *(float2*)&out[r1 + col] = make_float2(o[nt][2] * inv1, o[nt][3] * inv1);
    }
}

// ---------------------------------------------------------------------------
extern "C" void kernel_launch(void* const* d_in, const int* in_sizes, int n_in,
                              void* d_out, int out_size) {
    const float* x    = (const float*)d_in[0];
    const float* W    = (const float*)d_in[1];
    const float* bias = (const float*)d_in[2];
    float* out = (float*)d_out;

    split_x_kernel<<<(MTOT * DMODEL / 4) / 256, 256>>>(x);
    split_w_kernel<<<(NE * DMODEL) / 256, 256>>>(W);

    cudaFuncSetAttribute(qkv_mma_kernel, cudaFuncAttributeMaxDynamicSharedMemorySize,
                         QKV_SMEM);
    dim3 g1(128, 3);
    qkv_mma_kernel<<<g1, 256, QKV_SMEM>>>(bias);

    cudaFuncSetAttribute(attn_kernel, cudaFuncAttributeMaxDynamicSharedMemorySize,
                         ATTN_SMEM);
    dim3 g2(SEQ / 128, BATCH);
    attn_kernel<<<g2, 256, ATTN_SMEM>>>(out);
}